// round 16
// baseline (speedup 1.0000x reference)
#include <cuda_runtime.h>
#include <cuda_fp16.h>
#include <mma.h>
#include <cstdint>
#include <cstddef>

using namespace nvcuda;

#define B_ROWS 4096
#define D_IN   1024
#define D_H    4096
#define D_OUT  1024
#define NE     8
#define EH     32768
#define NACT   5

// GEMM tiling: CTA 128x128, 4 warps (2x2), warp tile 64x64, BK=64, 3 stages
#define BK  64
#define NSTG 3
#define LDA 72     // A smem row stride in halves (144B)
#define LDB 136    // B smem row stride in halves (272B)
#define ASTG_H (128 * LDA)            // 9216 halves
#define BSTG_H (BK * LDB)             // 8704 halves
#define STG_H  (ASTG_H + BSTG_H)      // 17920 halves = 35840 B
#define SMEM_BYTES (NSTG * STG_H * 2) // 107520 B (2 CTAs/SM: 215KB < 227KB)

// Fused prep grid layout: gate + x + w1 (w2 converts inside GEMM1's launch)
#define GB_GATE 512
#define N4X     (B_ROWS * D_IN / 4)    // 1048576
#define N4W     (NE * D_IN * D_H / 4)  // 8388608
#define PB_X0   GB_GATE
#define PB_W10  (PB_X0 + N4X / 256)    // 4608
#define PB_END  (PB_W10 + N4W / 256)   // 37376

// Scratch (device globals; no allocation allowed)
__device__ float  g_w[B_ROWS * NE];
__device__ int    g_cnt[NE];
__device__ int    g_rows[NE][B_ROWS];
__device__ int    g_slot[B_ROWS * NE];
__device__ __half g_xh[(size_t)B_ROWS * D_IN];
__device__ __half g_w1h[(size_t)NE * D_IN * D_H];
__device__ __half g_w2h[(size_t)EH * D_OUT];
__device__ __half g_hsh[(size_t)B_ROWS * EH];
__device__ float  g_eo[(size_t)NE * B_ROWS * D_OUT];   // slot-indexed, incl. w*b2

// ---------------------------------------------------------------------------
__device__ __forceinline__ void cp16h(__half* sdst, const __half* gsrc) {
    uint32_t s = (uint32_t)__cvta_generic_to_shared(sdst);
    asm volatile("cp.async.cg.shared.global [%0], [%1], 16;\n" :: "r"(s), "l"(gsrc));
}
#define CP_COMMIT()  asm volatile("cp.async.commit_group;\n")
#define CP_WAIT1()   asm volatile("cp.async.wait_group 1;\n" ::: "memory")

__device__ __forceinline__ void cvt_f4(const float4* __restrict__ src,
                                       uint2* __restrict__ dst, int i) {
    float4 v = src[i];
    union { __half2 h2[2]; uint2 u; } cvt;
    cvt.h2[0] = __floats2half2_rn(v.x, v.y);
    cvt.h2[1] = __floats2half2_rn(v.z, v.w);
    dst[i] = cvt.u;
}

// ---------------------------------------------------------------------------
// Fused prep: gate (blocks [0,GB_GATE)) + x/w1 fp32->fp16 conversions.
// ---------------------------------------------------------------------------
__global__ void prep_kernel(const float* __restrict__ x, const float* __restrict__ gw,
                            const float* __restrict__ gb,
                            const float4* __restrict__ w1f4) {
    const int b = blockIdx.x;
    const int tid = threadIdx.x;

    if (b >= GB_GATE) {
        if (b < PB_W10) cvt_f4((const float4*)x, (uint2*)g_xh, (b - PB_X0) * 256 + tid);
        else            cvt_f4(w1f4, (uint2*)g_w1h, (b - PB_W10) * 256 + tid);
        return;
    }

    // Gate section: one warp per row (proven)
    int warp = (b * 256 + tid) >> 5;
    int lane = tid & 31;
    const float* xr = x + (size_t)warp * D_IN;
    float acc[NE];
#pragma unroll
    for (int e = 0; e < NE; e++) acc[e] = 0.f;
    for (int i = lane; i < D_IN; i += 32) {
        float xv = xr[i];
        const float* g = gw + i * NE;
#pragma unroll
        for (int e = 0; e < NE; e++) acc[e] += xv * g[e];
    }
#pragma unroll
    for (int e = 0; e < NE; e++)
#pragma unroll
        for (int off = 16; off > 0; off >>= 1)
            acc[e] += __shfl_xor_sync(0xffffffffu, acc[e], off);
    if (lane == 0) {
        const float invT = 0.36787944117144233f;
        float p[NE]; float mx = -1e30f;
#pragma unroll
        for (int e = 0; e < NE; e++) { p[e] = (acc[e] + gb[e]) * invT; mx = fmaxf(mx, p[e]); }
        float sum = 0.f;
#pragma unroll
        for (int e = 0; e < NE; e++) { p[e] = expf(p[e] - mx); sum += p[e]; }
        float inv = 1.f / sum;
#pragma unroll
        for (int e = 0; e < NE; e++) p[e] *= inv;
        bool sel[NE];
#pragma unroll
        for (int e = 0; e < NE; e++) sel[e] = false;
        for (int t = 0; t < NACT; t++) {
            int bi = -1; float bv = -1.f;
#pragma unroll
            for (int e = 0; e < NE; e++)
                if (!sel[e] && p[e] > bv) { bv = p[e]; bi = e; }
            sel[bi] = true;
        }
        float ws = 0.f;
#pragma unroll
        for (int e = 0; e < NE; e++) if (sel[e]) ws += p[e];
        float wi = 1.f / (ws + 1e-8f);
#pragma unroll
        for (int e = 0; e < NE; e++) {
            float wv = sel[e] ? p[e] * wi : 0.f;
            g_w[warp * NE + e] = wv;
            if (sel[e]) {
                int pos = atomicAdd(&g_cnt[e], 1);
                g_rows[e][pos] = warp;
                g_slot[warp * NE + e] = pos;
            }
        }
    }
}

// ---------------------------------------------------------------------------
// Row-gathered fp16 GEMM: CTA 128x128, 4 warps (2x2), warp tile 64x64,
// BK=64, 3-stage cp.async (wait_group 1), 2 CTAs/SM.
// MODE 0: FFN1 -> g_hsh (scatter); extra z-slice (z==NE) converts w2.
// MODE 1: FFN2 -> g_eo[e] (slot-contiguous), epilogue adds w*b2.
// ---------------------------------------------------------------------------
template <int MODE>
__global__ void __launch_bounds__(128, 2) gemm_h(const float* __restrict__ bias,
                                                 const float4* __restrict__ w2f4) {
    extern __shared__ __align__(16) __half sm[];
    __shared__ int sidx[128];

    const int tid  = threadIdx.x;
    const int z    = blockIdx.z;                        // expert (or NE = w2 convert)
    const int row0 = blockIdx.y * 128;
    const int col0 = blockIdx.x * 128;

    if (MODE == 0 && z == NE) {
        // w2 fp32->fp16 conversion hidden under GEMM1: 1024 blocks x 128 thr x 64 f4
        int bid = blockIdx.y * gridDim.x + blockIdx.x;  // 0..1023
        int base = bid * 128 + tid;
#pragma unroll
        for (int k = 0; k < 64; k++)
            cvt_f4(w2f4, (uint2*)g_w2h, base + k * 131072);
        return;
    }

    const int cnt = g_cnt[z];
    if (row0 >= cnt) return;
    {
        int gr = row0 + tid;
        sidx[tid] = g_rows[z][gr < cnt ? gr : cnt - 1];
    }
    __syncthreads();

    const int    KT  = (MODE == 0) ? (D_IN / BK) : (D_H / BK);     // 16 / 64
    const size_t ldB = (MODE == 0) ? D_H : D_OUT;
    const __half* Ag = (MODE == 0) ? g_xh
                                   : g_hsh + (size_t)z * D_H;
    const __half* Bg = (MODE == 0) ? g_w1h + (size_t)z * D_IN * D_H + col0
                                   : g_w2h + (size_t)z * D_H * D_OUT + col0;

    wmma::fragment<wmma::accumulator, 16, 16, 16, float> c[4][4];
#pragma unroll
    for (int i = 0; i < 4; i++)
#pragma unroll
        for (int j = 0; j < 4; j++) wmma::fill_fragment(c[i][j], 0.f);

    auto load_stage = [&](int st, int k0) {
        __half* As = sm + st * STG_H;
        __half* Bs = As + ASTG_H;
#pragma unroll
        for (int f = tid; f < 1024; f += 128) {         // A: 128 rows x 8 segs
            int r = f >> 3, sg = f & 7;
            size_t arow = (MODE == 0) ? (size_t)sidx[r] * D_IN : (size_t)sidx[r] * EH;
            cp16h(&As[r * LDA + sg * 8], Ag + arow + k0 + sg * 8);
        }
#pragma unroll
        for (int f = tid; f < 1024; f += 128) {         // B: 64 rows x 16 segs
            int r = f >> 4, sg = f & 15;
            cp16h(&Bs[r * LDB + sg * 8], Bg + (size_t)(k0 + r) * ldB + sg * 8);
        }
        CP_COMMIT();
    };

    const int wid = tid >> 5, lane = tid & 31;
    const int wm = wid >> 1;      // 0..1 (64-row block)
    const int wn = wid & 1;       // 0..1 (64-col block)

    load_stage(0, 0);
    load_stage(1, BK);
    for (int kt = 0; kt < KT; kt++) {
        CP_WAIT1();               // load(kt) complete; load(kt+1) may be in flight
        __syncthreads();
        int ld = kt + 2;
        if (ld < KT) load_stage(ld % NSTG, ld * BK);
        else CP_COMMIT();         // keep group accounting uniform
        const __half* As = sm + (kt % NSTG) * STG_H;
        const __half* Bs = As + ASTG_H;
#pragma unroll
        for (int kk = 0; kk < BK; kk += 16) {
            wmma::fragment<wmma::matrix_a, 16, 16, 16, __half, wmma::row_major> a[4];
            wmma::fragment<wmma::matrix_b, 16, 16, 16, __half, wmma::row_major> b[4];
#pragma unroll
            for (int i = 0; i < 4; i++)
                wmma::load_matrix_sync(a[i], &As[(wm * 64 + i * 16) * LDA + kk], LDA);
#pragma unroll
            for (int j = 0; j < 4; j++)
                wmma::load_matrix_sync(b[j], &Bs[kk * LDB + wn * 64 + j * 16], LDB);
#pragma unroll
            for (int i = 0; i < 4; i++)
#pragma unroll
                for (int j = 0; j < 4; j++)
                    wmma::mma_sync(c[i][j], a[i], b[j], c[i][j]);
        }
    }
    __syncthreads();

    // Epilogue: per-warp 16x68 fp32 scratch on dead pipeline smem.
    float* scw = reinterpret_cast<float*>(sm) + wid * (16 * 68);
    const int gc0 = col0 + wn * 64 + lane * 2;
    const int bstride = (MODE == 0) ? D_H : D_OUT;
    const float bv0 = bias[(size_t)z * bstride + gc0];
    const float bv1 = bias[(size_t)z * bstride + gc0 + 1];

#pragma unroll
    for (int i = 0; i < 4; i++) {
#pragma unroll
        for (int j = 0; j < 4; j++)
            wmma::store_matrix_sync(scw + j * 16, c[i][j], 68, wmma::mem_row_major);
        __syncwarp();
        int slot0 = wm * 64 + i * 16;
#pragma unroll
        for (int r = 0; r < 16; r++) {
            int slot = slot0 + r;
            int gslot = row0 + slot;
            int row = sidx[slot];
            float wv = g_w[row * NE + z];
            float v0 = scw[r * 68 + lane * 2];
            float v1 = scw[r * 68 + lane * 2 + 1];
            if (MODE == 0) {
                if (gslot < cnt) {
                    float h0 = fmaxf(v0 + bv0, 0.f) * wv;
                    float h1 = fmaxf(v1 + bv1, 0.f) * wv;
                    *reinterpret_cast<__half2*>(&g_hsh[(size_t)row * EH + (size_t)z * D_H + gc0]) =
                        __floats2half2_rn(h0, h1);
                }
            } else {
                float2 o;
                o.x = v0 + wv * bv0;
                o.y = v1 + wv * bv1;
                *reinterpret_cast<float2*>(&g_eo[((size_t)z * B_ROWS + gslot) * D_OUT + gc0]) = o;
            }
        }
        __syncwarp();
    }
}

// ---------------------------------------------------------------------------
// finish (proven): per row sum per-camp expert slots, PH epilogue.
// ---------------------------------------------------------------------------
__global__ void finish_kernel(const float* __restrict__ alpha,
                              const float* __restrict__ beta, float* __restrict__ out) {
    __shared__ float sw[NE];
    __shared__ int   ssl[NE];
    __shared__ float red1[8], red2[8];
    __shared__ float sph;
    const int b = blockIdx.x, tid = threadIdx.x;
    if (tid < NE) {
        sw[tid]  = g_w[b * NE + tid];
        ssl[tid] = g_slot[b * NE + tid];
    }
    __syncthreads();
    const size_t SEC = (size_t)B_ROWS * D_OUT;
    float d[4]; float s1 = 0.f, s2 = 0.f;
#pragma unroll
    for (int t = 0; t < 4; t++) {
        int o = tid + 256 * t;
        float a = 0.f, g = 0.f;
#pragma unroll
        for (int e = 0; e < 4; e++) {
            if (sw[e] != 0.f)
                a += g_eo[((size_t)e * B_ROWS + ssl[e]) * D_OUT + o];
            if (sw[4 + e] != 0.f)
                g += g_eo[((size_t)(4 + e) * B_ROWS + ssl[4 + e]) * D_OUT + o];
        }
        out[SEC + (size_t)b * D_OUT + o] = a;
        out[2 * SEC + (size_t)b * D_OUT + o] = g;
        float dd = a - g; d[t] = dd; s1 += dd; s2 += dd * dd;
    }
#pragma unroll
    for (int off = 16; off > 0; off >>= 1) {
        s1 += __shfl_xor_sync(0xffffffffu, s1, off);
        s2 += __shfl_xor_sync(0xffffffffu, s2, off);
    }
    if ((tid & 31) == 0) { red1[tid >> 5] = s1; red2[tid >> 5] = s2; }
    __syncthreads();
    if (tid == 0) {
        float t1 = 0.f, t2 = 0.f;
#pragma unroll
        for (int w = 0; w < 8; w++) { t1 += red1[w]; t2 += red2[w]; }
        float l2 = sqrtf(t2);
        float mean = t1 * (1.f / D_OUT);
        float var = t2 * (1.f / D_OUT) - mean * mean;
        float zz = alpha[0] * (l2 * (1.f + var)) + beta[0];
        sph = 2.f / (1.f + expf(-zz));
    }
    __syncthreads();
    float ph = sph;
#pragma unroll
    for (int t = 0; t < 4; t++) {
        int o = tid + 256 * t;
        out[(size_t)b * D_OUT + o] = d[t] * ph;
    }
}

// ---------------------------------------------------------------------------
extern "C" void kernel_launch(void* const* d_in, const int* in_sizes, int n_in,
                              void* d_out, int out_size) {
    (void)in_sizes; (void)n_in; (void)out_size;
    const float* x  = (const float*)d_in[0];
    const float* gw = (const float*)d_in[1];
    const float* gb = (const float*)d_in[2];
    const float* w1 = (const float*)d_in[3];
    const float* b1 = (const float*)d_in[4];
    const float* w2 = (const float*)d_in[5];
    const float* b2 = (const float*)d_in[6];
    const float* pa = (const float*)d_in[7];
    const float* pb = (const float*)d_in[8];
    float* out = (float*)d_out;

    cudaFuncSetAttribute(gemm_h<0>, cudaFuncAttributeMaxDynamicSharedMemorySize, SMEM_BYTES);
    cudaFuncSetAttribute(gemm_h<1>, cudaFuncAttributeMaxDynamicSharedMemorySize, SMEM_BYTES);

    void* cnt_ptr = nullptr;
    cudaGetSymbolAddress(&cnt_ptr, g_cnt);
    cudaMemsetAsync(cnt_ptr, 0, NE * sizeof(int));

    prep_kernel<<<PB_END, 256>>>(x, gw, gb, (const float4*)w1);

    gemm_h<0><<<dim3(D_H / 128, B_ROWS / 128, NE + 1), 128, SMEM_BYTES>>>(b1, (const float4*)w2);
    gemm_h<1><<<dim3(D_OUT / 128, B_ROWS / 128, NE), 128, SMEM_BYTES>>>(b2, nullptr);
    finish_kernel<<<B_ROWS, 256>>>(pa, pb, out);
}

// round 17
// speedup vs baseline: 1.0257x; 1.0257x over previous
#include <cuda_runtime.h>
#include <cuda_fp16.h>
#include <mma.h>
#include <cstdint>
#include <cstddef>

using namespace nvcuda;

#define B_ROWS 4096
#define D_IN   1024
#define D_H    4096
#define D_OUT  1024
#define NE     8
#define EH     32768
#define NACT   5

// GEMM tiling (R15 proven): CTA 128x128, 4 warps (2x2), warp 64x64, BK=64, 2 stages
#define BK  64
#define LDA 72     // A smem row stride in halves (144B)
#define LDB 136    // B smem row stride in halves (272B)
#define ASTG_H (128 * LDA)            // 9216 halves
#define BSTG_H (BK * LDB)             // 8704 halves
#define STG_H  (ASTG_H + BSTG_H)      // 17920 halves = 35840 B
#define SMEM_BYTES (2 * STG_H * 2)    // 71680 B (2 CTAs/SM)

// Fused prep grid layout: gate + x + w1 (w2 converts inside GEMM1's launch)
#define GB_GATE 512
#define N4X     (B_ROWS * D_IN / 4)    // 1048576
#define N4W     (NE * D_IN * D_H / 4)  // 8388608
#define PB_X0   GB_GATE
#define PB_W10  (PB_X0 + N4X / 256)    // 4608
#define PB_END  (PB_W10 + N4W / 256)   // 37376

// Scratch (device globals; no allocation allowed)
__device__ float  g_w[B_ROWS * NE];
__device__ int    g_cnt[NE];
__device__ int    g_rows[NE][B_ROWS];
__device__ int    g_slot[B_ROWS * NE];
__device__ __half g_xh[(size_t)B_ROWS * D_IN];
__device__ __half g_w1h[(size_t)NE * D_IN * D_H];
__device__ __half g_w2h[(size_t)EH * D_OUT];
__device__ __half g_hsh[(size_t)B_ROWS * EH];
__device__ __half g_eoh[(size_t)NE * B_ROWS * D_OUT];  // fp16 slot-indexed, incl. w*b2

// ---------------------------------------------------------------------------
__device__ __forceinline__ void cp16h(__half* sdst, const __half* gsrc) {
    uint32_t s = (uint32_t)__cvta_generic_to_shared(sdst);
    asm volatile("cp.async.cg.shared.global [%0], [%1], 16;\n" :: "r"(s), "l"(gsrc));
}
#define CP_COMMIT()   asm volatile("cp.async.commit_group;\n")
#define CP_WAIT_ALL() asm volatile("cp.async.wait_group 0;\n" ::: "memory")

__device__ __forceinline__ void cvt_f4(const float4* __restrict__ src,
                                       uint2* __restrict__ dst, int i) {
    float4 v = src[i];
    union { __half2 h2[2]; uint2 u; } cvt;
    cvt.h2[0] = __floats2half2_rn(v.x, v.y);
    cvt.h2[1] = __floats2half2_rn(v.z, v.w);
    dst[i] = cvt.u;
}

// ---------------------------------------------------------------------------
// Fused prep: gate (blocks [0,GB_GATE)) + x/w1 fp32->fp16 conversions.
// ---------------------------------------------------------------------------
__global__ void prep_kernel(const float* __restrict__ x, const float* __restrict__ gw,
                            const float* __restrict__ gb,
                            const float4* __restrict__ w1f4) {
    const int b = blockIdx.x;
    const int tid = threadIdx.x;

    if (b >= GB_GATE) {
        if (b < PB_W10) cvt_f4((const float4*)x, (uint2*)g_xh, (b - PB_X0) * 256 + tid);
        else            cvt_f4(w1f4, (uint2*)g_w1h, (b - PB_W10) * 256 + tid);
        return;
    }

    // Gate section: one warp per row (proven)
    int warp = (b * 256 + tid) >> 5;
    int lane = tid & 31;
    const float* xr = x + (size_t)warp * D_IN;
    float acc[NE];
#pragma unroll
    for (int e = 0; e < NE; e++) acc[e] = 0.f;
    for (int i = lane; i < D_IN; i += 32) {
        float xv = xr[i];
        const float* g = gw + i * NE;
#pragma unroll
        for (int e = 0; e < NE; e++) acc[e] += xv * g[e];
    }
#pragma unroll
    for (int e = 0; e < NE; e++)
#pragma unroll
        for (int off = 16; off > 0; off >>= 1)
            acc[e] += __shfl_xor_sync(0xffffffffu, acc[e], off);
    if (lane == 0) {
        const float invT = 0.36787944117144233f;
        float p[NE]; float mx = -1e30f;
#pragma unroll
        for (int e = 0; e < NE; e++) { p[e] = (acc[e] + gb[e]) * invT; mx = fmaxf(mx, p[e]); }
        float sum = 0.f;
#pragma unroll
        for (int e = 0; e < NE; e++) { p[e] = expf(p[e] - mx); sum += p[e]; }
        float inv = 1.f / sum;
#pragma unroll
        for (int e = 0; e < NE; e++) p[e] *= inv;
        bool sel[NE];
#pragma unroll
        for (int e = 0; e < NE; e++) sel[e] = false;
        for (int t = 0; t < NACT; t++) {
            int bi = -1; float bv = -1.f;
#pragma unroll
            for (int e = 0; e < NE; e++)
                if (!sel[e] && p[e] > bv) { bv = p[e]; bi = e; }
            sel[bi] = true;
        }
        float ws = 0.f;
#pragma unroll
        for (int e = 0; e < NE; e++) if (sel[e]) ws += p[e];
        float wi = 1.f / (ws + 1e-8f);
#pragma unroll
        for (int e = 0; e < NE; e++) {
            float wv = sel[e] ? p[e] * wi : 0.f;
            g_w[warp * NE + e] = wv;
            if (sel[e]) {
                int pos = atomicAdd(&g_cnt[e], 1);
                g_rows[e][pos] = warp;
                g_slot[warp * NE + e] = pos;
            }
        }
    }
}

// ---------------------------------------------------------------------------
// Row-gathered fp16 GEMM (R15 core): CTA 128x128, 4 warps (2x2), warp 64x64,
// BK=64, 2-stage, 2 CTAs/SM.
// MODE 0: FFN1 -> g_hsh (scatter); extra z-slice (z==NE) converts w2.
// MODE 1: FFN2 -> g_eoh[e] fp16 (slot-contiguous), epilogue adds w*b2.
// ---------------------------------------------------------------------------
template <int MODE>
__global__ void __launch_bounds__(128, 2) gemm_h(const float* __restrict__ bias,
                                                 const float4* __restrict__ w2f4) {
    extern __shared__ __align__(16) __half sm[];
    __shared__ int sidx[128];

    const int tid  = threadIdx.x;
    const int z    = blockIdx.z;                        // expert (or NE = w2 convert)
    const int row0 = blockIdx.y * 128;
    const int col0 = blockIdx.x * 128;

    if (MODE == 0 && z == NE) {
        // w2 fp32->fp16 conversion hidden under GEMM1: 1024 blocks x 128 thr x 64 f4
        int bid = blockIdx.y * gridDim.x + blockIdx.x;  // 0..1023
        int base = bid * 128 + tid;
#pragma unroll
        for (int k = 0; k < 64; k++)
            cvt_f4(w2f4, (uint2*)g_w2h, base + k * 131072);
        return;
    }

    const int cnt = g_cnt[z];
    if (row0 >= cnt) return;
    {
        int gr = row0 + tid;
        sidx[tid] = g_rows[z][gr < cnt ? gr : cnt - 1];
    }
    __syncthreads();

    const int    KT  = (MODE == 0) ? (D_IN / BK) : (D_H / BK);     // 16 / 64
    const size_t ldB = (MODE == 0) ? D_H : D_OUT;
    const __half* Ag = (MODE == 0) ? g_xh
                                   : g_hsh + (size_t)z * D_H;
    const __half* Bg = (MODE == 0) ? g_w1h + (size_t)z * D_IN * D_H + col0
                                   : g_w2h + (size_t)z * D_H * D_OUT + col0;

    wmma::fragment<wmma::accumulator, 16, 16, 16, float> c[4][4];
#pragma unroll
    for (int i = 0; i < 4; i++)
#pragma unroll
        for (int j = 0; j < 4; j++) wmma::fill_fragment(c[i][j], 0.f);

    auto load_stage = [&](int st, int k0) {
        __half* As = sm + st * STG_H;
        __half* Bs = As + ASTG_H;
#pragma unroll
        for (int f = tid; f < 1024; f += 128) {         // A: 128 rows x 8 segs
            int r = f >> 3, sg = f & 7;
            size_t arow = (MODE == 0) ? (size_t)sidx[r] * D_IN : (size_t)sidx[r] * EH;
            cp16h(&As[r * LDA + sg * 8], Ag + arow + k0 + sg * 8);
        }
#pragma unroll
        for (int f = tid; f < 1024; f += 128) {         // B: 64 rows x 16 segs
            int r = f >> 4, sg = f & 15;
            cp16h(&Bs[r * LDB + sg * 8], Bg + (size_t)(k0 + r) * ldB + sg * 8);
        }
        CP_COMMIT();
    };

    const int wid = tid >> 5, lane = tid & 31;
    const int wm = wid >> 1;      // 0..1 (64-row block)
    const int wn = wid & 1;       // 0..1 (64-col block)

    load_stage(0, 0);
    for (int kt = 0; kt < KT; kt++) {
        CP_WAIT_ALL();
        __syncthreads();
        if (kt + 1 < KT) load_stage((kt + 1) & 1, (kt + 1) * BK);
        const __half* As = sm + (kt & 1) * STG_H;
        const __half* Bs = As + ASTG_H;
#pragma unroll
        for (int kk = 0; kk < BK; kk += 16) {
            wmma::fragment<wmma::matrix_a, 16, 16, 16, __half, wmma::row_major> a[4];
            wmma::fragment<wmma::matrix_b, 16, 16, 16, __half, wmma::row_major> b[4];
#pragma unroll
            for (int i = 0; i < 4; i++)
                wmma::load_matrix_sync(a[i], &As[(wm * 64 + i * 16) * LDA + kk], LDA);
#pragma unroll
            for (int j = 0; j < 4; j++)
                wmma::load_matrix_sync(b[j], &Bs[kk * LDB + wn * 64 + j * 16], LDB);
#pragma unroll
            for (int i = 0; i < 4; i++)
#pragma unroll
                for (int j = 0; j < 4; j++)
                    wmma::mma_sync(c[i][j], a[i], b[j], c[i][j]);
        }
    }
    __syncthreads();

    // Epilogue: per-warp 16x68 fp32 scratch on dead pipeline smem.
    float* scw = reinterpret_cast<float*>(sm) + wid * (16 * 68);
    const int gc0 = col0 + wn * 64 + lane * 2;
    const int bstride = (MODE == 0) ? D_H : D_OUT;
    const float bv0 = bias[(size_t)z * bstride + gc0];
    const float bv1 = bias[(size_t)z * bstride + gc0 + 1];

#pragma unroll
    for (int i = 0; i < 4; i++) {
#pragma unroll
        for (int j = 0; j < 4; j++)
            wmma::store_matrix_sync(scw + j * 16, c[i][j], 68, wmma::mem_row_major);
        __syncwarp();
        int slot0 = wm * 64 + i * 16;
#pragma unroll
        for (int r = 0; r < 16; r++) {
            int slot = slot0 + r;
            int gslot = row0 + slot;
            int row = sidx[slot];
            float wv = g_w[row * NE + z];
            float v0 = scw[r * 68 + lane * 2];
            float v1 = scw[r * 68 + lane * 2 + 1];
            if (MODE == 0) {
                if (gslot < cnt) {
                    float h0 = fmaxf(v0 + bv0, 0.f) * wv;
                    float h1 = fmaxf(v1 + bv1, 0.f) * wv;
                    *reinterpret_cast<__half2*>(&g_hsh[(size_t)row * EH + (size_t)z * D_H + gc0]) =
                        __floats2half2_rn(h0, h1);
                }
            } else {
                *reinterpret_cast<__half2*>(&g_eoh[((size_t)z * B_ROWS + gslot) * D_OUT + gc0]) =
                    __floats2half2_rn(v0 + wv * bv0, v1 + wv * bv1);
            }
        }
        __syncwarp();
    }
}

// ---------------------------------------------------------------------------
// finish: per row sum per-camp expert slots (fp16 g_eoh -> fp32), PH epilogue.
// ---------------------------------------------------------------------------
__global__ void finish_kernel(const float* __restrict__ alpha,
                              const float* __restrict__ beta, float* __restrict__ out) {
    __shared__ float sw[NE];
    __shared__ int   ssl[NE];
    __shared__ float red1[8], red2[8];
    __shared__ float sph;
    const int b = blockIdx.x, tid = threadIdx.x;
    if (tid < NE) {
        sw[tid]  = g_w[b * NE + tid];
        ssl[tid] = g_slot[b * NE + tid];
    }
    __syncthreads();
    const size_t SEC = (size_t)B_ROWS * D_OUT;
    float d[4]; float s1 = 0.f, s2 = 0.f;
#pragma unroll
    for (int t = 0; t < 4; t++) {
        int o = tid + 256 * t;
        float a = 0.f, g = 0.f;
#pragma unroll
        for (int e = 0; e < 4; e++) {
            if (sw[e] != 0.f)
                a += __half2float(g_eoh[((size_t)e * B_ROWS + ssl[e]) * D_OUT + o]);
            if (sw[4 + e] != 0.f)
                g += __half2float(g_eoh[((size_t)(4 + e) * B_ROWS + ssl[4 + e]) * D_OUT + o]);
        }
        out[SEC + (size_t)b * D_OUT + o] = a;
        out[2 * SEC + (size_t)b * D_OUT + o] = g;
        float dd = a - g; d[t] = dd; s1 += dd; s2 += dd * dd;
    }
#pragma unroll
    for (int off = 16; off > 0; off >>= 1) {
        s1 += __shfl_xor_sync(0xffffffffu, s1, off);
        s2 += __shfl_xor_sync(0xffffffffu, s2, off);
    }
    if ((tid & 31) == 0) { red1[tid >> 5] = s1; red2[tid >> 5] = s2; }
    __syncthreads();
    if (tid == 0) {
        float t1 = 0.f, t2 = 0.f;
#pragma unroll
        for (int w = 0; w < 8; w++) { t1 += red1[w]; t2 += red2[w]; }
        float l2 = sqrtf(t2);
        float mean = t1 * (1.f / D_OUT);
        float var = t2 * (1.f / D_OUT) - mean * mean;
        float zz = alpha[0] * (l2 * (1.f + var)) + beta[0];
        sph = 2.f / (1.f + expf(-zz));
    }
    __syncthreads();
    float ph = sph;
#pragma unroll
    for (int t = 0; t < 4; t++) {
        int o = tid + 256 * t;
        out[(size_t)b * D_OUT + o] = d[t] * ph;
    }
}

// ---------------------------------------------------------------------------
extern "C" void kernel_launch(void* const* d_in, const int* in_sizes, int n_in,
                              void* d_out, int out_size) {
    (void)in_sizes; (void)n_in; (void)out_size;
    const float* x  = (const float*)d_in[0];
    const float* gw = (const float*)d_in[1];
    const float* gb = (const float*)d_in[2];
    const float* w1 = (const float*)d_in[3];
    const float* b1 = (const float*)d_in[4];
    const float* w2 = (const float*)d_in[5];
    const float* b2 = (const float*)d_in[6];
    const float* pa = (const float*)d_in[7];
    const float* pb = (const float*)d_in[8];
    float* out = (float*)d_out;

    cudaFuncSetAttribute(gemm_h<0>, cudaFuncAttributeMaxDynamicSharedMemorySize, SMEM_BYTES);
    cudaFuncSetAttribute(gemm_h<1>, cudaFuncAttributeMaxDynamicSharedMemorySize, SMEM_BYTES);

    void* cnt_ptr = nullptr;
    cudaGetSymbolAddress(&cnt_ptr, g_cnt);
    cudaMemsetAsync(cnt_ptr, 0, NE * sizeof(int));

    prep_kernel<<<PB_END, 256>>>(x, gw, gb, (const float4*)w1);

    gemm_h<0><<<dim3(D_H / 128, B_ROWS / 128, NE + 1), 128, SMEM_BYTES>>>(b1, (const float4*)w2);
    gemm_h<1><<<dim3(D_OUT / 128, B_ROWS / 128, NE), 128, SMEM_BYTES>>>(b2, nullptr);
    finish_kernel<<<B_ROWS, 256>>>(pa, pb, out);
}